// round 15
// baseline (speedup 1.0000x reference)
#include <cuda_runtime.h>
#include <math.h>

// Problem constants (B=2, N=4096, C=256, K=64; hidden = 256, out = 256)
#define PB 2
#define PN 4096
#define PC 256
#define PK 64
#define NROW (PB * PK)       // 128
#define NS 8                 // segments per row
#define SEG (PN / NS)        // 512 points per segment

// Scratch (device globals; zero-initialized at load)
__device__ float4   g_part4[NROW * NS * 64];
__device__ int      g_cnt[NROW * NS];
__device__ unsigned g_done[NROW];     // self-resetting arrival counters

__global__ __launch_bounds__(256)
void roi_fused_lastcta(const float* __restrict__ points,   // (B, N, 3)
                       const float* __restrict__ feats,    // (B, N, C)
                       const float* __restrict__ props,    // (B, K, 7)
                       const float* __restrict__ W1,       // (C, 256)
                       const float* __restrict__ b1,
                       const float* __restrict__ W2,       // (256, 256)
                       const float* __restrict__ b2,
                       float* __restrict__ out)            // (B, K, 256)
{
    const int blk = blockIdx.x;      // bk * NS + s
    const int bk  = blk >> 3;
    const int s   = blk & (NS - 1);
    const int b   = bk / PK;
    const int t   = threadIdx.x;
    const int q   = t & 63;          // channel / output quad
    const int sl  = t >> 6;          // slice 0..3

    __shared__ int    s_idx[SEG];
    __shared__ int    s_count;
    __shared__ float  s_box[6];
    __shared__ float4 s_part[256];   // 4 KB (pool fold + MLP reduction scratch)
    __shared__ float4 s_x[64];       // 1 KB (MLP input / hidden vector)
    __shared__ int    s_last;
    __shared__ int    s_tot;

    // ================= Pooling (identical to R8) =================
    if (t == 0) s_count = 0;
    if (t < 3) {
        float c = props[bk * 7 + t];
        float h = props[bk * 7 + 3 + t] * 0.5f;
        s_box[t]     = c - h;
        s_box[t + 3] = c + h;
    }
    __syncthreads();

    const float lx = s_box[0], ly = s_box[1], lz = s_box[2];
    const float hx = s_box[3], hy = s_box[4], hz = s_box[5];

    const float* pb = points + (size_t)b * PN * 3;
    const int n0 = s * SEG;
    #pragma unroll
    for (int it = 0; it < SEG / 256; it++) {
        int n = n0 + it * 256 + t;
        float px = pb[n * 3 + 0];
        float py = pb[n * 3 + 1];
        float pz = pb[n * 3 + 2];
        bool inside = (px > lx) & (px < hx) &
                      (py > ly) & (py < hy) &
                      (pz > lz) & (pz < hz);
        if (inside) {
            int pos = atomicAdd(&s_count, 1);
            s_idx[pos] = n;
        }
    }
    __syncthreads();
    const int cnt = s_count;

    const float4* fb4 = (const float4*)(feats + (size_t)b * PN * PC);
    float4 acc = make_float4(-INFINITY, -INFINITY, -INFINITY, -INFINITY);
    {
        int i = sl;
        for (; i + 12 < cnt; i += 16) {
            int i0 = s_idx[i + 0];
            int i1 = s_idx[i + 4];
            int i2 = s_idx[i + 8];
            int i3 = s_idx[i + 12];
            float4 v0 = fb4[(size_t)i0 * 64 + q];
            float4 v1 = fb4[(size_t)i1 * 64 + q];
            float4 v2 = fb4[(size_t)i2 * 64 + q];
            float4 v3 = fb4[(size_t)i3 * 64 + q];
            acc.x = fmaxf(acc.x, fmaxf(fmaxf(v0.x, v1.x), fmaxf(v2.x, v3.x)));
            acc.y = fmaxf(acc.y, fmaxf(fmaxf(v0.y, v1.y), fmaxf(v2.y, v3.y)));
            acc.z = fmaxf(acc.z, fmaxf(fmaxf(v0.z, v1.z), fmaxf(v2.z, v3.z)));
            acc.w = fmaxf(acc.w, fmaxf(fmaxf(v0.w, v1.w), fmaxf(v2.w, v3.w)));
        }
        for (; i < cnt; i += 4) {
            float4 v = fb4[(size_t)s_idx[i] * 64 + q];
            acc.x = fmaxf(acc.x, v.x);
            acc.y = fmaxf(acc.y, v.y);
            acc.z = fmaxf(acc.z, v.z);
            acc.w = fmaxf(acc.w, v.w);
        }
    }
    s_part[t] = acc;
    __syncthreads();

    if (t < 64) {
        float4 a  = s_part[t];
        float4 c1 = s_part[64 + t];
        float4 c2 = s_part[128 + t];
        float4 c3 = s_part[192 + t];
        a.x = fmaxf(fmaxf(a.x, c1.x), fmaxf(c2.x, c3.x));
        a.y = fmaxf(fmaxf(a.y, c1.y), fmaxf(c2.y, c3.y));
        a.z = fmaxf(fmaxf(a.z, c1.z), fmaxf(c2.z, c3.z));
        a.w = fmaxf(fmaxf(a.w, c1.w), fmaxf(c2.w, c3.w));
        g_part4[(size_t)blk * 64 + t] = a;
    }
    if (t == 0) g_cnt[blk] = cnt;

    // ================= Arrival protocol =================
    __threadfence();                 // publish my partials (every thread)
    __syncthreads();                 // all fences done before the arrive
    if (t == 0) {
        unsigned old = atomicInc(&g_done[bk], NS - 1);   // wraps to 0 on 8th
        s_last = (old == NS - 1);
        __threadfence();             // acquire-ish: order atomic before reads
    }
    __syncthreads();
    if (!s_last) return;

    // ================= MLP tail (only the last CTA of each row) =================
    // fold the 8 segment partials (L2 reads, bypass L1)
    float4 xa;
    if (t < 64) {
        const float4* src = &g_part4[(size_t)bk * (NS * 64)];
        xa = __ldcg(&src[t]);
        #pragma unroll
        for (int g = 1; g < NS; g++) {
            float4 c = __ldcg(&src[g * 64 + t]);
            xa.x = fmaxf(xa.x, c.x);
            xa.y = fmaxf(xa.y, c.y);
            xa.z = fmaxf(xa.z, c.z);
            xa.w = fmaxf(xa.w, c.w);
        }
    }
    if (t == 64) {
        int c = 0;
        #pragma unroll
        for (int g = 0; g < NS; g++) c += __ldcg(&g_cnt[bk * NS + g]);
        s_tot = c;
    }
    __syncthreads();
    if (t < 64) {
        if (s_tot == 0) xa = make_float4(0.f, 0.f, 0.f, 0.f);
        s_x[t] = xa;
    }
    __syncthreads();

    // ---- layer 1: thread (q, sl): 64 c's, one output quad ----
    {
        const float4* W4 = (const float4*)W1;
        const float*  xf = (const float*)s_x;
        const int c0 = sl * 64;
        float4 a = make_float4(0.f, 0.f, 0.f, 0.f);
        #pragma unroll 16
        for (int c = 0; c < 64; c++) {
            float4 w = W4[(size_t)(c0 + c) * 64 + q];
            float f = xf[c0 + c];
            a.x = fmaf(f, w.x, a.x);
            a.y = fmaf(f, w.y, a.y);
            a.z = fmaf(f, w.z, a.z);
            a.w = fmaf(f, w.w, a.w);
        }
        s_part[t] = a;
    }
    __syncthreads();
    if (t < 64) {
        float4 a  = s_part[t];
        float4 c1 = s_part[64 + t];
        float4 c2 = s_part[128 + t];
        float4 c3 = s_part[192 + t];
        float4 bb = ((const float4*)b1)[t];
        a.x = fmaxf(a.x + c1.x + c2.x + c3.x + bb.x, 0.f);
        a.y = fmaxf(a.y + c1.y + c2.y + c3.y + bb.y, 0.f);
        a.z = fmaxf(a.z + c1.z + c2.z + c3.z + bb.z, 0.f);
        a.w = fmaxf(a.w + c1.w + c2.w + c3.w + bb.w, 0.f);
        s_x[t] = a;                  // hidden vector replaces input
    }
    __syncthreads();

    // ---- layer 2 ----
    {
        const float4* W4 = (const float4*)W2;
        const float*  xf = (const float*)s_x;
        const int c0 = sl * 64;
        float4 a = make_float4(0.f, 0.f, 0.f, 0.f);
        #pragma unroll 16
        for (int c = 0; c < 64; c++) {
            float4 w = W4[(size_t)(c0 + c) * 64 + q];
            float f = xf[c0 + c];
            a.x = fmaf(f, w.x, a.x);
            a.y = fmaf(f, w.y, a.y);
            a.z = fmaf(f, w.z, a.z);
            a.w = fmaf(f, w.w, a.w);
        }
        s_part[t] = a;
    }
    __syncthreads();
    if (t < 64) {
        float4 a  = s_part[t];
        float4 c1 = s_part[64 + t];
        float4 c2 = s_part[128 + t];
        float4 c3 = s_part[192 + t];
        float4 bb = ((const float4*)b2)[t];
        a.x = fmaxf(a.x + c1.x + c2.x + c3.x + bb.x, 0.f);
        a.y = fmaxf(a.y + c1.y + c2.y + c3.y + bb.y, 0.f);
        a.z = fmaxf(a.z + c1.z + c2.z + c3.z + bb.z, 0.f);
        a.w = fmaxf(a.w + c1.w + c2.w + c3.w + bb.w, 0.f);
        ((float4*)out)[(size_t)bk * 64 + t] = a;
    }
}

extern "C" void kernel_launch(void* const* d_in, const int* in_sizes, int n_in,
                              void* d_out, int out_size)
{
    const float* points = (const float*)d_in[0];   // (B, N, 3)
    const float* feats  = (const float*)d_in[1];   // (B, N, C)
    const float* props  = (const float*)d_in[2];   // (B, K, 7)
    const float* W1     = (const float*)d_in[3];   // (C, 256)
    const float* b1     = (const float*)d_in[4];   // (256)
    const float* W2     = (const float*)d_in[5];   // (256, 256)
    const float* b2     = (const float*)d_in[6];   // (256)
    float*       out    = (float*)d_out;           // (B, K, 256)

    roi_fused_lastcta<<<NROW * NS, 256>>>(points, feats, props, W1, b1, W2, b2, out);
}

// round 16
// speedup vs baseline: 1.7230x; 1.7230x over previous
#include <cuda_runtime.h>
#include <cuda_fp16.h>
#include <math.h>

// Problem constants (B=2, N=4096, C=256, K=64; hidden = 256, out = 256)
#define PB 2
#define PN 4096
#define PC 256
#define PK 64
#define NS 8                 // split-K over points: 8 segments of 512 points
#define SEG (PN / NS)        // 512 points per segment
#define NW (2 * 256 * 256)   // total weight elements (W1 + W2)

// Scratch: partial maxima [B*K][NS][64 float4], counts, fp16 weight mirror
__device__ float4 g_part4[PB * PK * NS * 64];
__device__ int    g_cnt[PB * PK * NS];
__device__ __half g_wh[NW];          // [0:65536) = W1, [65536:131072) = W2

// ---------------- Kernel A: segment pooling + weight conversion ----------------
__global__ __launch_bounds__(256)
void pool_partial_kernel(const float* __restrict__ points,   // (B, N, 3)
                         const float* __restrict__ feats,    // (B, N, C)
                         const float* __restrict__ props,    // (B, K, 7)
                         const float* __restrict__ W1,       // (C, 256)
                         const float* __restrict__ W2)       // (256, 256)
{
    const int blk = blockIdx.x;      // bk * NS + s
    const int bk  = blk >> 3;
    const int s   = blk & (NS - 1);
    const int b   = bk / PK;
    const int t   = threadIdx.x;
    const int q   = t & 63;          // channel quad
    const int sl  = t >> 6;          // slice 0..3

    __shared__ int    s_idx[SEG];
    __shared__ int    s_count;
    __shared__ float  s_box[6];
    __shared__ float4 s_part[256];

    // ---- fp16 weight conversion stripe: 128 floats per CTA ----
    {
        int i = blk * 128 + (t & 127);
        if (t < 128) {
            float v = (i < 65536) ? W1[i] : W2[i - 65536];
            g_wh[i] = __float2half(v);
        }
    }

    if (t == 0) s_count = 0;
    if (t < 3) {
        float c = props[bk * 7 + t];
        float h = props[bk * 7 + 3 + t] * 0.5f;
        s_box[t]     = c - h;
        s_box[t + 3] = c + h;
    }
    __syncthreads();

    const float lx = s_box[0], ly = s_box[1], lz = s_box[2];
    const float hx = s_box[3], hy = s_box[4], hz = s_box[5];

    const float* pb = points + (size_t)b * PN * 3;
    const int n0 = s * SEG;
    #pragma unroll
    for (int it = 0; it < SEG / 256; it++) {
        int n = n0 + it * 256 + t;
        float px = pb[n * 3 + 0];
        float py = pb[n * 3 + 1];
        float pz = pb[n * 3 + 2];
        bool inside = (px > lx) & (px < hx) &
                      (py > ly) & (py < hy) &
                      (pz > lz) & (pz < hz);
        if (inside) {
            int pos = atomicAdd(&s_count, 1);
            s_idx[pos] = n;
        }
    }
    __syncthreads();
    const int cnt = s_count;

    const float4* fb4 = (const float4*)(feats + (size_t)b * PN * PC);
    float4 acc = make_float4(-INFINITY, -INFINITY, -INFINITY, -INFINITY);
    {
        int i = sl;
        for (; i + 12 < cnt; i += 16) {
            int i0 = s_idx[i + 0];
            int i1 = s_idx[i + 4];
            int i2 = s_idx[i + 8];
            int i3 = s_idx[i + 12];
            float4 v0 = fb4[(size_t)i0 * 64 + q];
            float4 v1 = fb4[(size_t)i1 * 64 + q];
            float4 v2 = fb4[(size_t)i2 * 64 + q];
            float4 v3 = fb4[(size_t)i3 * 64 + q];
            acc.x = fmaxf(acc.x, fmaxf(fmaxf(v0.x, v1.x), fmaxf(v2.x, v3.x)));
            acc.y = fmaxf(acc.y, fmaxf(fmaxf(v0.y, v1.y), fmaxf(v2.y, v3.y)));
            acc.z = fmaxf(acc.z, fmaxf(fmaxf(v0.z, v1.z), fmaxf(v2.z, v3.z)));
            acc.w = fmaxf(acc.w, fmaxf(fmaxf(v0.w, v1.w), fmaxf(v2.w, v3.w)));
        }
        for (; i < cnt; i += 4) {
            float4 v = fb4[(size_t)s_idx[i] * 64 + q];
            acc.x = fmaxf(acc.x, v.x);
            acc.y = fmaxf(acc.y, v.y);
            acc.z = fmaxf(acc.z, v.z);
            acc.w = fmaxf(acc.w, v.w);
        }
    }
    s_part[t] = acc;
    __syncthreads();

    if (t < 64) {
        float4 a  = s_part[t];
        float4 c1 = s_part[64 + t];
        float4 c2 = s_part[128 + t];
        float4 c3 = s_part[192 + t];
        a.x = fmaxf(fmaxf(a.x, c1.x), fmaxf(c2.x, c3.x));
        a.y = fmaxf(fmaxf(a.y, c1.y), fmaxf(c2.y, c3.y));
        a.z = fmaxf(fmaxf(a.z, c1.z), fmaxf(c2.z, c3.z));
        a.w = fmaxf(fmaxf(a.w, c1.w), fmaxf(c2.w, c3.w));
        g_part4[(size_t)blk * 64 + t] = a;
    }
    if (t == 0) g_cnt[blk] = cnt;
}

// ---------------- Kernel B: reduce partials + MLP (fp16 weights) ----------------
#define THREADS 1024
#define NSL 16

__global__ __launch_bounds__(THREADS)
void mlp_kernel(const float* __restrict__ b1,
                const float* __restrict__ b2,
                float* __restrict__ out)        // (B, K, 256)
{
    const int bk = blockIdx.x;
    const int t  = threadIdx.x;
    const int q  = t & 63;
    const int sl = t >> 6;

    __shared__ float4 s_part[THREADS];   // 16 KB scratch
    __shared__ float4 s_vec[64];
    __shared__ float4 s_h[64];
    __shared__ int    s_cnt;

    // load the 8 partial vectors (contiguous 512 float4) coalesced
    if (t < NS * 64) {
        s_part[t] = g_part4[(size_t)bk * (NS * 64) + t];
    }
    if (t == 0) {
        int c = 0;
        #pragma unroll
        for (int i = 0; i < NS; i++) c += g_cnt[bk * NS + i];
        s_cnt = c;
    }
    __syncthreads();

    if (t < 64) {
        float4 a = s_part[t];
        #pragma unroll
        for (int g = 1; g < NS; g++) {
            float4 c = s_part[g * 64 + t];
            a.x = fmaxf(a.x, c.x);
            a.y = fmaxf(a.y, c.y);
            a.z = fmaxf(a.z, c.z);
            a.w = fmaxf(a.w, c.w);
        }
        if (s_cnt == 0) a = make_float4(0.f, 0.f, 0.f, 0.f);
        s_vec[t] = a;
    }
    __syncthreads();

    // ---- layer 1: h = relu(pooled @ W1 + b1); fp16 weight quads (8B loads) ----
    {
        const uint2* W1h = (const uint2*)(g_wh);            // quad = 4 halves
        const float* vecf = (const float*)s_vec;
        float4 ha = make_float4(0.f, 0.f, 0.f, 0.f);
        const int c0 = sl * 16;
        #pragma unroll
        for (int c = 0; c < 16; c++) {
            float f = vecf[c0 + c];                         // warp-uniform LDS
            uint2 wp = W1h[(size_t)(c0 + c) * 64 + q];
            float2 w01 = __half22float2(*reinterpret_cast<__half2*>(&wp.x));
            float2 w23 = __half22float2(*reinterpret_cast<__half2*>(&wp.y));
            ha.x = fmaf(f, w01.x, ha.x);
            ha.y = fmaf(f, w01.y, ha.y);
            ha.z = fmaf(f, w23.x, ha.z);
            ha.w = fmaf(f, w23.y, ha.w);
        }
        s_part[t] = ha;
    }
    __syncthreads();
    if (t < 64) {
        float4 a = s_part[t];
        #pragma unroll
        for (int g = 1; g < NSL; g++) {
            float4 c = s_part[g * 64 + t];
            a.x += c.x; a.y += c.y; a.z += c.z; a.w += c.w;
        }
        float4 bb = ((const float4*)b1)[t];
        a.x = fmaxf(a.x + bb.x, 0.f);
        a.y = fmaxf(a.y + bb.y, 0.f);
        a.z = fmaxf(a.z + bb.z, 0.f);
        a.w = fmaxf(a.w + bb.w, 0.f);
        s_h[t] = a;
    }
    __syncthreads();

    // ---- layer 2: out = relu(h @ W2 + b2) ----
    {
        const uint2* W2h = (const uint2*)(g_wh + 65536);
        const float* hf = (const float*)s_h;
        float4 oa = make_float4(0.f, 0.f, 0.f, 0.f);
        const int c0 = sl * 16;
        #pragma unroll
        for (int c = 0; c < 16; c++) {
            float f = hf[c0 + c];
            uint2 wp = W2h[(size_t)(c0 + c) * 64 + q];
            float2 w01 = __half22float2(*reinterpret_cast<__half2*>(&wp.x));
            float2 w23 = __half22float2(*reinterpret_cast<__half2*>(&wp.y));
            oa.x = fmaf(f, w01.x, oa.x);
            oa.y = fmaf(f, w01.y, oa.y);
            oa.z = fmaf(f, w23.x, oa.z);
            oa.w = fmaf(f, w23.y, oa.w);
        }
        s_part[t] = oa;
    }
    __syncthreads();
    if (t < 64) {
        float4 a = s_part[t];
        #pragma unroll
        for (int g = 1; g < NSL; g++) {
            float4 c = s_part[g * 64 + t];
            a.x += c.x; a.y += c.y; a.z += c.z; a.w += c.w;
        }
        float4 bb = ((const float4*)b2)[t];
        a.x = fmaxf(a.x + bb.x, 0.f);
        a.y = fmaxf(a.y + bb.y, 0.f);
        a.z = fmaxf(a.z + bb.z, 0.f);
        a.w = fmaxf(a.w + bb.w, 0.f);
        ((float4*)out)[(size_t)bk * 64 + t] = a;
    }
}

extern "C" void kernel_launch(void* const* d_in, const int* in_sizes, int n_in,
                              void* d_out, int out_size)
{
    const float* points = (const float*)d_in[0];   // (B, N, 3)
    const float* feats  = (const float*)d_in[1];   // (B, N, C)
    const float* props  = (const float*)d_in[2];   // (B, K, 7)
    const float* W1     = (const float*)d_in[3];   // (C, 256)
    const float* b1     = (const float*)d_in[4];   // (256)
    const float* W2     = (const float*)d_in[5];   // (256, 256)
    const float* b2     = (const float*)d_in[6];   // (256)
    float*       out    = (float*)d_out;           // (B, K, 256)

    pool_partial_kernel<<<PB * PK * NS, 256>>>(points, feats, props, W1, W2);
    mlp_kernel<<<PB * PK, THREADS>>>(b1, b2, out);
}

// round 17
// speedup vs baseline: 1.7663x; 1.0251x over previous
#include <cuda_runtime.h>
#include <math.h>

// Problem constants (B=2, N=4096, C=256, K=64; hidden = 256, out = 256)
#define PB 2
#define PN 4096
#define PC 256
#define PK 64
#define NS 8                 // split-K over points: 8 segments of 512 points
#define SEG (PN / NS)        // 512 points per segment

// Scratch: partial maxima [B*K][NS][64 float4] and counts [B*K][NS]
__device__ float4 g_part4[PB * PK * NS * 64];
__device__ int    g_cnt[PB * PK * NS];

// ---------------- Kernel A: segment pooling (R8-proven) ----------------
__global__ __launch_bounds__(256)
void pool_partial_kernel(const float* __restrict__ points,   // (B, N, 3)
                         const float* __restrict__ feats,    // (B, N, C)
                         const float* __restrict__ props)    // (B, K, 7)
{
    const int blk = blockIdx.x;      // bk * NS + s
    const int bk  = blk >> 3;
    const int s   = blk & (NS - 1);
    const int b   = bk / PK;
    const int t   = threadIdx.x;
    const int q   = t & 63;          // channel quad
    const int sl  = t >> 6;          // slice 0..3

    __shared__ int    s_idx[SEG];
    __shared__ int    s_count;
    __shared__ float  s_box[6];
    __shared__ float4 s_part[256];

    if (t == 0) s_count = 0;
    if (t < 3) {
        float c = props[bk * 7 + t];
        float h = props[bk * 7 + 3 + t] * 0.5f;
        s_box[t]     = c - h;
        s_box[t + 3] = c + h;
    }
    __syncthreads();

    const float lx = s_box[0], ly = s_box[1], lz = s_box[2];
    const float hx = s_box[3], hy = s_box[4], hz = s_box[5];

    const float* pb = points + (size_t)b * PN * 3;
    const int n0 = s * SEG;
    #pragma unroll
    for (int it = 0; it < SEG / 256; it++) {
        int n = n0 + it * 256 + t;
        float px = pb[n * 3 + 0];
        float py = pb[n * 3 + 1];
        float pz = pb[n * 3 + 2];
        bool inside = (px > lx) & (px < hx) &
                      (py > ly) & (py < hy) &
                      (pz > lz) & (pz < hz);
        if (inside) {
            int pos = atomicAdd(&s_count, 1);
            s_idx[pos] = n;
        }
    }
    __syncthreads();
    const int cnt = s_count;

    const float4* fb4 = (const float4*)(feats + (size_t)b * PN * PC);
    float4 acc = make_float4(-INFINITY, -INFINITY, -INFINITY, -INFINITY);
    {
        int i = sl;
        for (; i + 12 < cnt; i += 16) {
            int i0 = s_idx[i + 0];
            int i1 = s_idx[i + 4];
            int i2 = s_idx[i + 8];
            int i3 = s_idx[i + 12];
            float4 v0 = fb4[(size_t)i0 * 64 + q];
            float4 v1 = fb4[(size_t)i1 * 64 + q];
            float4 v2 = fb4[(size_t)i2 * 64 + q];
            float4 v3 = fb4[(size_t)i3 * 64 + q];
            acc.x = fmaxf(acc.x, fmaxf(fmaxf(v0.x, v1.x), fmaxf(v2.x, v3.x)));
            acc.y = fmaxf(acc.y, fmaxf(fmaxf(v0.y, v1.y), fmaxf(v2.y, v3.y)));
            acc.z = fmaxf(acc.z, fmaxf(fmaxf(v0.z, v1.z), fmaxf(v2.z, v3.z)));
            acc.w = fmaxf(acc.w, fmaxf(fmaxf(v0.w, v1.w), fmaxf(v2.w, v3.w)));
        }
        for (; i < cnt; i += 4) {
            float4 v = fb4[(size_t)s_idx[i] * 64 + q];
            acc.x = fmaxf(acc.x, v.x);
            acc.y = fmaxf(acc.y, v.y);
            acc.z = fmaxf(acc.z, v.z);
            acc.w = fmaxf(acc.w, v.w);
        }
    }
    s_part[t] = acc;
    __syncthreads();

    if (t < 64) {
        float4 a  = s_part[t];
        float4 c1 = s_part[64 + t];
        float4 c2 = s_part[128 + t];
        float4 c3 = s_part[192 + t];
        a.x = fmaxf(fmaxf(a.x, c1.x), fmaxf(c2.x, c3.x));
        a.y = fmaxf(fmaxf(a.y, c1.y), fmaxf(c2.y, c3.y));
        a.z = fmaxf(fmaxf(a.z, c1.z), fmaxf(c2.z, c3.z));
        a.w = fmaxf(fmaxf(a.w, c1.w), fmaxf(c2.w, c3.w));
        g_part4[(size_t)blk * 64 + t] = a;
    }
    if (t == 0) g_cnt[blk] = cnt;

    // Signal the dependent MLP kernel that this block's results are committed.
    cudaTriggerProgrammaticLaunchCompletion();
}

// ---------------- Kernel B: reduce partials + MLP (R8-proven, PDL-gated) ----------------
#define THREADS 1024
#define NSL 16

__global__ __launch_bounds__(THREADS)
void mlp_kernel(const float* __restrict__ W1,   // (C, 256)
                const float* __restrict__ b1,
                const float* __restrict__ W2,   // (256, 256)
                const float* __restrict__ b2,
                float* __restrict__ out)        // (B, K, 256)
{
    const int bk = blockIdx.x;
    const int t  = threadIdx.x;
    const int q  = t & 63;
    const int sl = t >> 6;

    __shared__ float4 s_part[THREADS];   // 16 KB scratch
    __shared__ float4 s_vec[64];
    __shared__ float4 s_h[64];
    __shared__ int    s_cnt;

    // Wait until the pool kernel's memory is visible (PDL gate).
    cudaGridDependencySynchronize();

    // load the 8 partial vectors (contiguous 512 float4) coalesced
    if (t < NS * 64) {
        s_part[t] = g_part4[(size_t)bk * (NS * 64) + t];
    }
    if (t == 0) {
        int c = 0;
        #pragma unroll
        for (int i = 0; i < NS; i++) c += g_cnt[bk * NS + i];
        s_cnt = c;
    }
    __syncthreads();

    if (t < 64) {
        float4 a = s_part[t];
        #pragma unroll
        for (int g = 1; g < NS; g++) {
            float4 c = s_part[g * 64 + t];
            a.x = fmaxf(a.x, c.x);
            a.y = fmaxf(a.y, c.y);
            a.z = fmaxf(a.z, c.z);
            a.w = fmaxf(a.w, c.w);
        }
        if (s_cnt == 0) a = make_float4(0.f, 0.f, 0.f, 0.f);
        s_vec[t] = a;
    }
    __syncthreads();

    // ---- layer 1: h = relu(pooled @ W1 + b1); slice sl covers 16 c's ----
    {
        const float4* W1_4 = (const float4*)W1;
        const float*  vecf = (const float*)s_vec;
        float4 ha = make_float4(0.f, 0.f, 0.f, 0.f);
        const int c0 = sl * 16;
        #pragma unroll
        for (int c = 0; c < 16; c++) {
            float f = vecf[c0 + c];                  // warp-uniform broadcast
            float4 w = W1_4[(size_t)(c0 + c) * 64 + q];
            ha.x = fmaf(f, w.x, ha.x);
            ha.y = fmaf(f, w.y, ha.y);
            ha.z = fmaf(f, w.z, ha.z);
            ha.w = fmaf(f, w.w, ha.w);
        }
        s_part[t] = ha;
    }
    __syncthreads();
    if (t < 64) {
        float4 a = s_part[t];
        #pragma unroll
        for (int g = 1; g < NSL; g++) {
            float4 c = s_part[g * 64 + t];
            a.x += c.x; a.y += c.y; a.z += c.z; a.w += c.w;
        }
        float4 bb = ((const float4*)b1)[t];
        a.x = fmaxf(a.x + bb.x, 0.f);
        a.y = fmaxf(a.y + bb.y, 0.f);
        a.z = fmaxf(a.z + bb.z, 0.f);
        a.w = fmaxf(a.w + bb.w, 0.f);
        s_h[t] = a;
    }
    __syncthreads();

    // ---- layer 2: out = relu(h @ W2 + b2) ----
    {
        const float4* W2_4 = (const float4*)W2;
        const float*  hf = (const float*)s_h;
        float4 oa = make_float4(0.f, 0.f, 0.f, 0.f);
        const int c0 = sl * 16;
        #pragma unroll
        for (int c = 0; c < 16; c++) {
            float f = hf[c0 + c];
            float4 w = W2_4[(size_t)(c0 + c) * 64 + q];
            oa.x = fmaf(f, w.x, oa.x);
            oa.y = fmaf(f, w.y, oa.y);
            oa.z = fmaf(f, w.z, oa.z);
            oa.w = fmaf(f, w.w, oa.w);
        }
        s_part[t] = oa;
    }
    __syncthreads();
    if (t < 64) {
        float4 a = s_part[t];
        #pragma unroll
        for (int g = 1; g < NSL; g++) {
            float4 c = s_part[g * 64 + t];
            a.x += c.x; a.y += c.y; a.z += c.z; a.w += c.w;
        }
        float4 bb = ((const float4*)b2)[t];
        a.x = fmaxf(a.x + bb.x, 0.f);
        a.y = fmaxf(a.y + bb.y, 0.f);
        a.z = fmaxf(a.z + bb.z, 0.f);
        a.w = fmaxf(a.w + bb.w, 0.f);
        ((float4*)out)[(size_t)bk * 64 + t] = a;
    }
}

extern "C" void kernel_launch(void* const* d_in, const int* in_sizes, int n_in,
                              void* d_out, int out_size)
{
    const float* points = (const float*)d_in[0];   // (B, N, 3)
    const float* feats  = (const float*)d_in[1];   // (B, N, C)
    const float* props  = (const float*)d_in[2];   // (B, K, 7)
    const float* W1     = (const float*)d_in[3];   // (C, 256)
    const float* b1     = (const float*)d_in[4];   // (256)
    const float* W2     = (const float*)d_in[5];   // (256, 256)
    const float* b2     = (const float*)d_in[6];   // (256)
    float*       out    = (float*)d_out;           // (B, K, 256)

    pool_partial_kernel<<<PB * PK * NS, 256>>>(points, feats, props);

    // Launch the MLP with Programmatic Dependent Launch so its prologue
    // overlaps the pool kernel's tail; correctness gated by
    // cudaGridDependencySynchronize() inside the kernel.
    cudaLaunchConfig_t cfg = {};
    cfg.gridDim  = dim3(PB * PK, 1, 1);
    cfg.blockDim = dim3(THREADS, 1, 1);
    cfg.dynamicSmemBytes = 0;
    cfg.stream = 0;
    cudaLaunchAttribute attrs[1];
    attrs[0].id = cudaLaunchAttributeProgrammaticStreamSerialization;
    attrs[0].val.programmaticStreamSerializationAllowed = 1;
    cfg.attrs = attrs;
    cfg.numAttrs = 1;
    cudaLaunchKernelEx(&cfg, mlp_kernel, W1, b1, W2, b2, out);
}